// round 3
// baseline (speedup 1.0000x reference)
#include <cuda_runtime.h>

#define BATCH 32
#define NIN   2312
#define NHID  512
#define NOUT  10
#define TT    350
#define TKLEN 100

#define THETA 10.0f
#define D_SR  0.90483741803595952f     // exp(-0.1)
#define C_SR  0.27182818284590452f     // e/10
#define E10   4.5399929762484854e-05f  // exp(-10)
#define D_REF 0.36787944117144233f     // exp(-1)
#define C_REF -54.365636569180902f     // -20e

#define TTILE 32   // t per spgemm1 block
#define CI    64   // i chunk for mask staging

// scratch (allocation-free: device globals)
__device__ float g_W1T[(size_t)NIN * NHID];         // [i][h]
__device__ float g_G1[(size_t)BATCH * TT * NHID];   // [b][t][h]
__device__ float g_S1[(size_t)BATCH * TT * NHID];   // [b][t][h]
__device__ float g_G2[(size_t)BATCH * TT * NOUT];   // [b][t][o]

// ---------------------------------------------------------------------------
// Transpose W1 [NHID][NIN] -> W1T [NIN][NHID]
// ---------------------------------------------------------------------------
__global__ void __launch_bounds__(256) w1t_kernel(const float* __restrict__ W1) {
    __shared__ float tile[32][33];
    int i0 = blockIdx.x * 32;   // NIN dim
    int h0 = blockIdx.y * 32;   // NHID dim
    int lx = threadIdx.x & 31;
    int ly = threadIdx.x >> 5;  // 0..7

    #pragma unroll
    for (int r = 0; r < 4; r++) {
        int h = h0 + ly + r * 8;
        int i = i0 + lx;
        tile[ly + r * 8][lx] = (i < NIN) ? W1[(size_t)h * NIN + i] : 0.f;
    }
    __syncthreads();
    #pragma unroll
    for (int r = 0; r < 4; r++) {
        int i = i0 + ly + r * 8;
        int h = h0 + lx;
        if (i < NIN) g_W1T[(size_t)i * NHID + h] = tile[lx][ly + r * 8];
    }
}

// ---------------------------------------------------------------------------
// Sparse GEMM1, t-tiled. Block = (b, 32 consecutive t). 8 warps, warp w owns
// t = t0 + 4w .. 4w+3. Thread h-slice: 4 float4s at h = q*128 + lane*4.
// Phase A: build 32-bit activity masks per input row i (coalesced X reads).
// Phase B: each warp gathers W1T rows active for its 4 t's (ascending i order
// -> deterministic, same accumulation order as dense reference loop).
// ---------------------------------------------------------------------------
__device__ __forceinline__ void add4(float4& a, const float4& r) {
    a.x += r.x; a.y += r.y; a.z += r.z; a.w += r.w;
}

__global__ void __launch_bounds__(256) spgemm1_kernel(const float* __restrict__ X) {
    __shared__ unsigned smask[CI];

    const int b    = blockIdx.y;
    const int t0   = blockIdx.x * TTILE;
    const int warp = threadIdx.x >> 5;
    const int lane = threadIdx.x & 31;

    float4 acc[4][4];   // [t_local][q]
    #pragma unroll
    for (int tl = 0; tl < 4; tl++)
        #pragma unroll
        for (int q = 0; q < 4; q++)
            acc[tl][q] = make_float4(0.f, 0.f, 0.f, 0.f);

    const float* xbase = X + (size_t)b * NIN * TT;

    for (int c = 0; c < NIN; c += CI) {
        if (threadIdx.x < CI) smask[threadIdx.x] = 0u;
        __syncthreads();

        // Phase A: masks. idx enumerates (i_local, quad): CI*8 = 512 units.
        #pragma unroll
        for (int r = 0; r < (CI * 8) / 256; r++) {
            int idx = threadIdx.x + r * 256;
            int il  = idx >> 3;         // 0..CI-1
            int q   = idx & 7;          // 0..7 (4 t's each)
            int i   = c + il;
            int tq  = t0 + q * 4;
            unsigned nib = 0;
            if (i < NIN && tq < TT) {
                const float* xr = xbase + (size_t)i * TT + tq;
                if (tq + 3 < TT) {
                    float2 v0 = *(const float2*)(xr);
                    float2 v1 = *(const float2*)(xr + 2);
                    nib = (unsigned)(v0.x != 0.f) | ((unsigned)(v0.y != 0.f) << 1)
                        | ((unsigned)(v1.x != 0.f) << 2) | ((unsigned)(v1.y != 0.f) << 3);
                } else {
                    #pragma unroll
                    for (int e = 0; e < 4; e++)
                        if (tq + e < TT && xr[e] != 0.f) nib |= 1u << e;
                }
            }
            if (nib) atomicOr(&smask[il], nib << (q * 4));
        }
        __syncthreads();

        // Phase B: each warp consumes rows active for its 4-bit t-submask.
        #pragma unroll 1
        for (int g = 0; g < CI; g += 32) {
            unsigned mi  = smask[g + lane];
            unsigned sub = (mi >> (warp * 4)) & 0xFu;
            unsigned act = __ballot_sync(0xffffffffu, sub != 0u);
            while (act) {
                int j = __ffs(act) - 1;
                act &= act - 1;
                unsigned s = __shfl_sync(0xffffffffu, sub, j);
                const float4* row = (const float4*)(g_W1T + (size_t)(c + g + j) * NHID);
                float4 r0 = row[lane];
                float4 r1 = row[lane + 32];
                float4 r2 = row[lane + 64];
                float4 r3 = row[lane + 96];
                if (s & 1u) { add4(acc[0][0], r0); add4(acc[0][1], r1); add4(acc[0][2], r2); add4(acc[0][3], r3); }
                if (s & 2u) { add4(acc[1][0], r0); add4(acc[1][1], r1); add4(acc[1][2], r2); add4(acc[1][3], r3); }
                if (s & 4u) { add4(acc[2][0], r0); add4(acc[2][1], r1); add4(acc[2][2], r2); add4(acc[2][3], r3); }
                if (s & 8u) { add4(acc[3][0], r0); add4(acc[3][1], r1); add4(acc[3][2], r2); add4(acc[3][3], r3); }
            }
        }
        __syncthreads();
    }

    // Epilogue: coalesced float4 stores, h = (lane + 32q)*4
    #pragma unroll
    for (int tl = 0; tl < 4; tl++) {
        int t = t0 + warp * 4 + tl;
        if (t < TT) {
            float4* out = (float4*)(g_G1 + ((size_t)b * TT + t) * NHID);
            out[lane]      = acc[tl][0];
            out[lane + 32] = acc[tl][1];
            out[lane + 64] = acc[tl][2];
            out[lane + 96] = acc[tl][3];
        }
    }
}

// ---------------------------------------------------------------------------
// scan1: per (b,h) channel — truncated-alpha psp (4-state IIR) fused with
// threshold/refractory spike scan. Writes s1 in {0,1}.
// ---------------------------------------------------------------------------
__global__ void __launch_bounds__(256) scan1_kernel() {
    int idx = blockIdx.x * blockDim.x + threadIdx.x;
    if (idx >= BATCH * NHID) return;
    int b = idx / NHID;
    int h = idx - b * NHID;

    const float* __restrict__ g = g_G1 + (size_t)b * TT * NHID + h;
    float*       __restrict__ s = g_S1 + (size_t)b * TT * NHID + h;

    float pa = 0.f, pb = 0.f;
    float qa = 0.f, qb = 0.f;
    float ra = 0.f, rb = 0.f;

    #pragma unroll 5
    for (int t = 0; t < TT; t++) {
        float gv = __ldg(&g[(size_t)t * NHID]);
        float gd = (t >= TKLEN) ? __ldg(&g[(size_t)(t - TKLEN) * NHID]) : 0.f;

        float pa_o = pa, qa_o = qa, ra_o = ra;
        pa = fmaf(D_SR, pa_o, gv);
        pb = fmaf(D_SR, pb, D_SR * pa_o);
        qa = fmaf(D_SR, qa_o, gd);
        qb = fmaf(D_SR, qb, D_SR * qa_o);

        float y = C_SR * (pb - E10 * fmaf(100.f, qa, qb));
        float u = fmaf(C_REF, rb, y);
        float sp = (u >= THETA) ? 1.f : 0.f;

        ra = fmaf(D_REF, ra_o, sp);
        rb = fmaf(D_REF, rb, D_REF * ra_o);

        s[(size_t)t * NHID] = sp;
    }
}

// ---------------------------------------------------------------------------
// GEMM2: warp per (b,t), full-chip grid. G2[b][t][o] = sum_h W2[o][h]*S1[b][t][h]
// ---------------------------------------------------------------------------
__global__ void __launch_bounds__(256) gemm2_kernel(const float* __restrict__ W2) {
    __shared__ float w2s[NOUT * NHID];   // 20 KB
    for (int i = threadIdx.x; i < NOUT * NHID; i += 256) w2s[i] = W2[i];
    __syncthreads();

    const int b    = blockIdx.y;
    const int t    = blockIdx.x * 8 + (threadIdx.x >> 5);
    const int lane = threadIdx.x & 31;
    if (t >= TT) return;

    const float* srow = g_S1 + ((size_t)b * TT + t) * NHID;

    float acc[NOUT];
    #pragma unroll
    for (int o = 0; o < NOUT; o++) acc[o] = 0.f;

    for (int h = lane; h < NHID; h += 32) {
        float sv = srow[h];
        #pragma unroll
        for (int o = 0; o < NOUT; o++)
            acc[o] = fmaf(w2s[o * NHID + h], sv, acc[o]);
    }
    #pragma unroll
    for (int off = 16; off > 0; off >>= 1)
        #pragma unroll
        for (int o = 0; o < NOUT; o++)
            acc[o] += __shfl_xor_sync(0xffffffffu, acc[o], off);

    if (lane == 0) {
        #pragma unroll
        for (int o = 0; o < NOUT; o++)
            g_G2[((size_t)b * TT + t) * NOUT + o] = acc[o];
    }
}

// ---------------------------------------------------------------------------
// scan2: block per b. Stage G2[b] (14 KB) into smem, then 10 threads run the
// spike scan with LDS-latency state updates. Writes out [b][o][t].
// ---------------------------------------------------------------------------
__global__ void __launch_bounds__(128) scan2_kernel(float* __restrict__ out) {
    __shared__ float g2s[TT * NOUT];
    const int b = blockIdx.x;

    const float* src = g_G2 + (size_t)b * TT * NOUT;
    for (int i = threadIdx.x; i < TT * NOUT; i += 128) g2s[i] = src[i];
    __syncthreads();

    if (threadIdx.x < NOUT) {
        const int o = threadIdx.x;
        float* y_out = out + ((size_t)b * NOUT + o) * TT;

        float pa = 0.f, pb = 0.f, qa = 0.f, qb = 0.f, ra = 0.f, rb = 0.f;
        for (int t = 0; t < TT; t++) {
            float gv = g2s[t * NOUT + o];
            float gd = (t >= TKLEN) ? g2s[(t - TKLEN) * NOUT + o] : 0.f;

            float pa_o = pa, qa_o = qa, ra_o = ra;
            pa = fmaf(D_SR, pa_o, gv);
            pb = fmaf(D_SR, pb, D_SR * pa_o);
            qa = fmaf(D_SR, qa_o, gd);
            qb = fmaf(D_SR, qb, D_SR * qa_o);

            float y = C_SR * (pb - E10 * fmaf(100.f, qa, qb));
            float u = fmaf(C_REF, rb, y);
            float sp = (u >= THETA) ? 1.f : 0.f;

            ra = fmaf(D_REF, ra_o, sp);
            rb = fmaf(D_REF, rb, D_REF * ra_o);

            y_out[t] = sp;
        }
    }
}

// ---------------------------------------------------------------------------
extern "C" void kernel_launch(void* const* d_in, const int* in_sizes, int n_in,
                              void* d_out, int out_size) {
    const float* X  = (const float*)d_in[0];   // [32][2312][350]
    const float* W1 = (const float*)d_in[1];   // [512][2312]
    const float* W2 = (const float*)d_in[2];   // [10][512]
    float* out = (float*)d_out;                // [32][10][350]

    dim3 gT((NIN + 31) / 32, NHID / 32);
    w1t_kernel<<<gT, 256>>>(W1);

    dim3 gS((TT + TTILE - 1) / TTILE, BATCH);
    spgemm1_kernel<<<gS, 256>>>(X);

    scan1_kernel<<<(BATCH * NHID + 255) / 256, 256>>>();

    dim3 gG2((TT + 7) / 8, BATCH);
    gemm2_kernel<<<gG2, 256>>>(W2);

    scan2_kernel<<<BATCH, 128>>>(out);
}

// round 4
// speedup vs baseline: 1.7728x; 1.7728x over previous
#include <cuda_runtime.h>

#define BATCH 32
#define NIN   2312
#define NHID  512
#define NOUT  10
#define TT    350
#define TKLEN 100
#define NIG   73    // ceil(NIN/32) mask words per (b,t)

#define THETA 10.0f
#define D_SR  0.90483741803595952f     // exp(-0.1)
#define C_SR  0.27182818284590452f     // e/10
#define E10   4.5399929762484854e-05f  // exp(-10)
#define D_REF 0.36787944117144233f     // exp(-1)
#define C_REF -54.365636569180902f     // -20e

// scratch (allocation-free: device globals)
__device__ float    g_W1T[(size_t)NIN * NHID];          // [i][h]
__device__ unsigned g_M  [(size_t)BATCH * TT * NIG];    // X bitmasks [b][t][ig]
__device__ float    g_G1 [(size_t)BATCH * TT * NHID];   // [b][t][h]
__device__ unsigned g_S1b[(size_t)BATCH * TT * (NHID/32)]; // s1 bitmasks [b][t][hg]
__device__ float    g_G2 [(size_t)BATCH * TT * NOUT];   // [b][t][o]

// ---------------------------------------------------------------------------
// Transpose W1 [NHID][NIN] -> W1T [NIN][NHID]
// ---------------------------------------------------------------------------
__global__ void __launch_bounds__(256) w1t_kernel(const float* __restrict__ W1) {
    __shared__ float tile[32][33];
    int i0 = blockIdx.x * 32;
    int h0 = blockIdx.y * 32;
    int lx = threadIdx.x & 31;
    int ly = threadIdx.x >> 5;

    #pragma unroll
    for (int r = 0; r < 4; r++) {
        int h = h0 + ly + r * 8;
        int i = i0 + lx;
        tile[ly + r * 8][lx] = (i < NIN) ? W1[(size_t)h * NIN + i] : 0.f;
    }
    __syncthreads();
    #pragma unroll
    for (int r = 0; r < 4; r++) {
        int i = i0 + ly + r * 8;
        int h = h0 + lx;
        if (i < NIN) g_W1T[(size_t)i * NHID + h] = tile[lx][ly + r * 8];
    }
}

// ---------------------------------------------------------------------------
// Mask build: block per (b, ig). Stage 32 rows of X (350 floats each) in smem
// coalescedly, then thread t packs the 32-bit word -> g_M[b][t][ig].
// ---------------------------------------------------------------------------
__global__ void __launch_bounds__(352) maskbuild_kernel(const float* __restrict__ X) {
    __shared__ float xs[32][TT];
    const int ig = blockIdx.x;
    const int b  = blockIdx.y;
    const int tid = threadIdx.x;

    #pragma unroll 1
    for (int j = 0; j < 32; j++) {
        int i = ig * 32 + j;
        if (tid < TT)
            xs[j][tid] = (i < NIN) ? X[((size_t)b * NIN + i) * TT + tid] : 0.f;
    }
    __syncthreads();

    if (tid < TT) {
        unsigned w = 0;
        #pragma unroll
        for (int j = 0; j < 32; j++)
            if (xs[j][tid] != 0.f) w |= 1u << j;
        g_M[((size_t)b * TT + tid) * NIG + ig] = w;
    }
}

// ---------------------------------------------------------------------------
// Sparse GEMM1: warp per (b,t); 8 consecutive t per block. Reads bitmasks
// (1 coalesced word per lane) and gathers active W1T rows in ascending-i
// order (deterministic). 16 FADD per row per thread — issue floor ~35us.
// ---------------------------------------------------------------------------
__device__ __forceinline__ void add4(float4& a, const float4& r) {
    a.x += r.x; a.y += r.y; a.z += r.z; a.w += r.w;
}

__global__ void __launch_bounds__(256) spgemm1_kernel() {
    const int warp = threadIdx.x >> 5;
    const int lane = threadIdx.x & 31;
    const int b = blockIdx.y;
    const int t = blockIdx.x * 8 + warp;
    if (t >= TT) return;

    const unsigned* __restrict__ mrow = g_M + ((size_t)b * TT + t) * NIG;

    float4 acc0 = make_float4(0.f, 0.f, 0.f, 0.f);
    float4 acc1 = acc0, acc2 = acc0, acc3 = acc0;

    #pragma unroll
    for (int cb = 0; cb < 96; cb += 32) {
        unsigned mw = (cb + lane < NIG) ? mrow[cb + lane] : 0u;
        unsigned act = __ballot_sync(0xffffffffu, mw != 0u);
        while (act) {
            int j = __ffs(act) - 1;
            act &= act - 1;
            unsigned w = __shfl_sync(0xffffffffu, mw, j);
            int ibase = (cb + j) * 32;
            while (w) {
                int bit = __ffs(w) - 1;
                w &= w - 1;
                const float4* row = (const float4*)(g_W1T + (size_t)(ibase + bit) * NHID);
                float4 r0 = row[lane];
                float4 r1 = row[lane + 32];
                float4 r2 = row[lane + 64];
                float4 r3 = row[lane + 96];
                add4(acc0, r0); add4(acc1, r1); add4(acc2, r2); add4(acc3, r3);
            }
        }
    }

    float4* out = (float4*)(g_G1 + ((size_t)b * TT + t) * NHID);
    out[lane]      = acc0;
    out[lane + 32] = acc1;
    out[lane + 64] = acc2;
    out[lane + 96] = acc3;
}

// ---------------------------------------------------------------------------
// scan1: per (b,h) channel — truncated-alpha psp (4-state IIR) fused with
// threshold/refractory scan. Emits spike BITMASKS via warp ballot.
// ---------------------------------------------------------------------------
__global__ void __launch_bounds__(256) scan1_kernel() {
    int idx = blockIdx.x * blockDim.x + threadIdx.x;   // exactly BATCH*NHID
    int b = idx >> 9;            // /512
    int h = idx & 511;
    int lane = threadIdx.x & 31;
    int hg = h >> 5;

    const float* __restrict__ g = g_G1 + (size_t)b * TT * NHID + h;
    unsigned* __restrict__ sb = g_S1b + (size_t)b * TT * (NHID/32) + hg;

    float pa = 0.f, pb = 0.f;
    float qa = 0.f, qb = 0.f;
    float ra = 0.f, rb = 0.f;

    #pragma unroll 5
    for (int t = 0; t < TT; t++) {
        float gv = __ldg(&g[(size_t)t * NHID]);
        float gd = (t >= TKLEN) ? __ldg(&g[(size_t)(t - TKLEN) * NHID]) : 0.f;

        float pa_o = pa, qa_o = qa, ra_o = ra;
        pa = fmaf(D_SR, pa_o, gv);
        pb = fmaf(D_SR, pb, D_SR * pa_o);
        qa = fmaf(D_SR, qa_o, gd);
        qb = fmaf(D_SR, qb, D_SR * qa_o);

        float y = C_SR * (pb - E10 * fmaf(100.f, qa, qb));
        float u = fmaf(C_REF, rb, y);
        float sp = (u >= THETA) ? 1.f : 0.f;

        ra = fmaf(D_REF, ra_o, sp);
        rb = fmaf(D_REF, rb, D_REF * ra_o);

        unsigned wbits = __ballot_sync(0xffffffffu, sp != 0.f);
        if (lane == 0) sb[(size_t)t * (NHID/32)] = wbits;
    }
}

// ---------------------------------------------------------------------------
// GEMM2 (sparse): warp per (b,t). Spikes are exactly 1.0 -> G2[t][o] is a sum
// of W2^T rows over active h (ascending order). Lanes 0..9 hold outputs.
// ---------------------------------------------------------------------------
__global__ void __launch_bounds__(256) gemm2_kernel(const float* __restrict__ W2) {
    __shared__ float w2t[NHID * NOUT];   // transposed [h][o], 20 KB
    for (int i = threadIdx.x; i < NOUT * NHID; i += 256) {
        int o = i / NHID, h = i - o * NHID;
        w2t[h * NOUT + o] = W2[i];
    }
    __syncthreads();

    const int b = blockIdx.y;
    const int t = blockIdx.x * 8 + (threadIdx.x >> 5);
    const int lane = threadIdx.x & 31;
    if (t >= TT) return;

    const unsigned* srow = g_S1b + ((size_t)b * TT + t) * (NHID/32);
    unsigned mw = (lane < NHID/32) ? srow[lane] : 0u;

    float acc = 0.f;   // lane<10: accumulator for o=lane
    unsigned act = __ballot_sync(0xffffffffu, mw != 0u);
    while (act) {
        int j = __ffs(act) - 1;
        act &= act - 1;
        unsigned w = __shfl_sync(0xffffffffu, mw, j);
        int hbase = j * 32;
        while (w) {
            int bit = __ffs(w) - 1;
            w &= w - 1;
            if (lane < NOUT) acc += w2t[(hbase + bit) * NOUT + lane];
        }
    }
    if (lane < NOUT)
        g_G2[((size_t)b * TT + t) * NOUT + lane] = acc;
}

// ---------------------------------------------------------------------------
// scan2: block per b. Stage G2[b] into smem, 10 threads run the spike scan.
// ---------------------------------------------------------------------------
__global__ void __launch_bounds__(128) scan2_kernel(float* __restrict__ out) {
    __shared__ float g2s[TT * NOUT];
    const int b = blockIdx.x;

    const float* src = g_G2 + (size_t)b * TT * NOUT;
    for (int i = threadIdx.x; i < TT * NOUT; i += 128) g2s[i] = src[i];
    __syncthreads();

    if (threadIdx.x < NOUT) {
        const int o = threadIdx.x;
        float* y_out = out + ((size_t)b * NOUT + o) * TT;

        float pa = 0.f, pb = 0.f, qa = 0.f, qb = 0.f, ra = 0.f, rb = 0.f;
        for (int t = 0; t < TT; t++) {
            float gv = g2s[t * NOUT + o];
            float gd = (t >= TKLEN) ? g2s[(t - TKLEN) * NOUT + o] : 0.f;

            float pa_o = pa, qa_o = qa, ra_o = ra;
            pa = fmaf(D_SR, pa_o, gv);
            pb = fmaf(D_SR, pb, D_SR * pa_o);
            qa = fmaf(D_SR, qa_o, gd);
            qb = fmaf(D_SR, qb, D_SR * qa_o);

            float y = C_SR * (pb - E10 * fmaf(100.f, qa, qb));
            float u = fmaf(C_REF, rb, y);
            float sp = (u >= THETA) ? 1.f : 0.f;

            ra = fmaf(D_REF, ra_o, sp);
            rb = fmaf(D_REF, rb, D_REF * ra_o);

            y_out[t] = sp;
        }
    }
}

// ---------------------------------------------------------------------------
extern "C" void kernel_launch(void* const* d_in, const int* in_sizes, int n_in,
                              void* d_out, int out_size) {
    const float* X  = (const float*)d_in[0];   // [32][2312][350]
    const float* W1 = (const float*)d_in[1];   // [512][2312]
    const float* W2 = (const float*)d_in[2];   // [10][512]
    float* out = (float*)d_out;                // [32][10][350]

    dim3 gT((NIN + 31) / 32, NHID / 32);
    w1t_kernel<<<gT, 256>>>(W1);

    dim3 gM(NIG, BATCH);
    maskbuild_kernel<<<gM, 352>>>(X);

    dim3 gS((TT + 7) / 8, BATCH);
    spgemm1_kernel<<<gS, 256>>>();

    scan1_kernel<<<(BATCH * NHID) / 256, 256>>>();

    dim3 gG2((TT + 7) / 8, BATCH);
    gemm2_kernel<<<gG2, 256>>>(W2);

    scan2_kernel<<<BATCH, 128>>>(out);
}